// round 2
// baseline (speedup 1.0000x reference)
#include <cuda_runtime.h>
#include <math.h>

#define N_NODES 100000
#define N_EDGES 600000
#define DIM     128      // IN = OUT = ED = 128
#define TD      64       // time enc channels
#define MSGD    64
#define HEADS   2
#define CHAN    64       // per-head channels

// ---------------- scratch (device globals; no runtime allocation) ----------
__device__ float g_q[(size_t)N_NODES * DIM];
__device__ float g_k[(size_t)N_NODES * DIM];
__device__ float g_v[(size_t)N_NODES * DIM];
__device__ float g_e[(size_t)N_EDGES * DIM];
__device__ float g_ex[(size_t)N_EDGES * HEADS];
__device__ float g_denom[(size_t)N_NODES * HEADS];

// ---------------- kernel Z: zero softmax denominators ----------------------
__global__ void zero_denom_kernel() {
    int i = blockIdx.x * blockDim.x + threadIdx.x;
    int n = N_NODES * HEADS;
    for (; i < n; i += gridDim.x * blockDim.x) g_denom[i] = 0.0f;
}

// ---------------- kernel A: fused node GEMMs (q,k,v,skip) ------------------
// out[m] = x @ W[m] + b[m], M=100000, N=128, K=128, four matrices.
// Block: 64 rows x 128 cols, 256 threads, each thread 8x4 register tile.
#define SMEM_A_BYTES ((64 * 132 + 128 * 128) * 4)

__global__ void __launch_bounds__(256)
node_gemm_kernel(const float* __restrict__ x,
                 const float* __restrict__ Wq, const float* __restrict__ bq,
                 const float* __restrict__ Wk, const float* __restrict__ bk,
                 const float* __restrict__ Wv, const float* __restrict__ bv,
                 const float* __restrict__ Wskip, const float* __restrict__ bskip,
                 float* __restrict__ out_skip)
{
    extern __shared__ float smem[];
    float (*sA)[132] = (float(*)[132])smem;                 // 64 x 128 (padded)
    float (*sB)[128] = (float(*)[128])(smem + 64 * 132);    // 128 x 128

    const int tid = threadIdx.x;
    const int tx  = tid & 31;          // col group (4 cols)
    const int ty  = tid >> 5;          // row group (8 rows)
    const int row0 = blockIdx.x * 64;

    // load x tile
    for (int v = tid; v < 64 * 32; v += 256) {
        int r = v >> 5, c4 = (v & 31) * 4;
        int row = row0 + r;
        float4 val = make_float4(0.f, 0.f, 0.f, 0.f);
        if (row < N_NODES)
            val = *(const float4*)&x[(size_t)row * DIM + c4];
        *(float4*)&sA[r][c4] = val;
    }

    const float* Ws[4] = {Wq, Wk, Wv, Wskip};
    const float* bs[4] = {bq, bk, bv, bskip};
    float* outs[4]; outs[0] = g_q; outs[1] = g_k; outs[2] = g_v; outs[3] = out_skip;

    for (int m = 0; m < 4; m++) {
        __syncthreads();
        const float* W = Ws[m];
        for (int v = tid; v < 128 * 32; v += 256) {
            int r = v >> 5, c4 = (v & 31) * 4;
            *(float4*)&sB[r][c4] = *(const float4*)&W[r * DIM + c4];
        }
        __syncthreads();

        float acc[8][4];
        #pragma unroll
        for (int r = 0; r < 8; r++) { acc[r][0]=acc[r][1]=acc[r][2]=acc[r][3]=0.f; }

        #pragma unroll 4
        for (int k0 = 0; k0 < 128; k0 += 4) {
            float4 a[8];
            #pragma unroll
            for (int r = 0; r < 8; r++) a[r] = *(float4*)&sA[ty * 8 + r][k0];
            #pragma unroll
            for (int kk = 0; kk < 4; kk++) {
                float4 b = *(float4*)&sB[k0 + kk][tx * 4];
                #pragma unroll
                for (int r = 0; r < 8; r++) {
                    float av = (kk == 0) ? a[r].x : (kk == 1) ? a[r].y : (kk == 2) ? a[r].z : a[r].w;
                    acc[r][0] += av * b.x; acc[r][1] += av * b.y;
                    acc[r][2] += av * b.z; acc[r][3] += av * b.w;
                }
            }
        }

        float4 bias = *(const float4*)&bs[m][tx * 4];
        float* O = outs[m];
        #pragma unroll
        for (int r = 0; r < 8; r++) {
            int row = row0 + ty * 8 + r;
            if (row < N_NODES) {
                float4 o = make_float4(acc[r][0] + bias.x, acc[r][1] + bias.y,
                                       acc[r][2] + bias.z, acc[r][3] + bias.w);
                *(float4*)&O[(size_t)row * DIM + tx * 4] = o;
            }
        }
    }
}

// ---------------- kernel B: edge pass 1 ------------------------------------
// Per 64-edge tile: build edge_attr = [cos(rel_t*wt+bt) | msg] in smem,
// e = attr @ We (We smem-resident), store e; then alpha = q_i.(k_j+e)/8,
// ex = exp(alpha), atomicAdd denom.
#define SMEM_B_BYTES ((64 * 132 * 2 + 128 * 128) * 4)

__global__ void __launch_bounds__(256)
edge_pass1_kernel(const float* __restrict__ last_update,
                  const int* __restrict__ edge_index,   // [2*E]: src then dst
                  const float* __restrict__ t,
                  const float* __restrict__ msg,
                  const float* __restrict__ wt,
                  const float* __restrict__ bt,
                  const float* __restrict__ We)
{
    extern __shared__ float smem[];
    float (*sAttr)[132] = (float(*)[132])smem;                          // 64 x 128
    float (*sW)[128]    = (float(*)[128])(smem + 64 * 132);             // 128 x 128
    float (*sE)[132]    = (float(*)[132])(smem + 64 * 132 + 128 * 128); // 64 x 128
    __shared__ float s_rel[64];

    const int tid = threadIdx.x;
    const int tx  = tid & 31;
    const int ty  = tid >> 5;
    const int e0  = blockIdx.x * 64;
    const int* src = edge_index;
    const int* dst = edge_index + N_EDGES;

    // load We
    for (int v = tid; v < 128 * 32; v += 256) {
        int r = v >> 5, c4 = (v & 31) * 4;
        *(float4*)&sW[r][c4] = *(const float4*)&We[r * DIM + c4];
    }
    // relative times
    if (tid < 64) {
        int e = e0 + tid;
        s_rel[tid] = last_update[src[e]] - t[e];
    }
    __syncthreads();

    // build edge_attr tile
    for (int idx = tid; idx < 64 * 128; idx += 256) {
        int i = idx >> 7, c = idx & 127;
        float val;
        if (c < TD) val = cosf(s_rel[i] * wt[c] + bt[c]);
        else        val = msg[(size_t)(e0 + i) * MSGD + (c - TD)];
        sAttr[i][c] = val;
    }
    __syncthreads();

    // GEMM 64 x 128 x 128
    float acc[8][4];
    #pragma unroll
    for (int r = 0; r < 8; r++) { acc[r][0]=acc[r][1]=acc[r][2]=acc[r][3]=0.f; }

    #pragma unroll 4
    for (int k0 = 0; k0 < 128; k0 += 4) {
        float4 a[8];
        #pragma unroll
        for (int r = 0; r < 8; r++) a[r] = *(float4*)&sAttr[ty * 8 + r][k0];
        #pragma unroll
        for (int kk = 0; kk < 4; kk++) {
            float4 b = *(float4*)&sW[k0 + kk][tx * 4];
            #pragma unroll
            for (int r = 0; r < 8; r++) {
                float av = (kk == 0) ? a[r].x : (kk == 1) ? a[r].y : (kk == 2) ? a[r].z : a[r].w;
                acc[r][0] += av * b.x; acc[r][1] += av * b.y;
                acc[r][2] += av * b.z; acc[r][3] += av * b.w;
            }
        }
    }

    // e -> smem + global scratch
    #pragma unroll
    for (int r = 0; r < 8; r++) {
        int i = ty * 8 + r;
        float4 o = make_float4(acc[r][0], acc[r][1], acc[r][2], acc[r][3]);
        *(float4*)&sE[i][tx * 4] = o;
        *(float4*)&g_e[(size_t)(e0 + i) * DIM + tx * 4] = o;
    }
    __syncthreads();

    // alpha per (edge, head): 128 tasks over 8 warps
    for (int task = ty; task < 64 * HEADS; task += 8) {
        int i = task >> 1, h = task & 1;
        int e = e0 + i;
        int s = src[e], d = dst[e];
        const float* qp = g_q + (size_t)d * DIM + h * CHAN;
        const float* kp = g_k + (size_t)s * DIM + h * CHAN;
        float sum = qp[tx]      * (kp[tx]      + sE[i][h * CHAN + tx]) +
                    qp[tx + 32] * (kp[tx + 32] + sE[i][h * CHAN + tx + 32]);
        #pragma unroll
        for (int o = 16; o > 0; o >>= 1) sum += __shfl_xor_sync(0xffffffffu, sum, o);
        if (tx == 0) {
            float ex = expf(sum * 0.125f);   // / sqrt(64)
            g_ex[(size_t)e * HEADS + h] = ex;
            atomicAdd(&g_denom[(size_t)d * HEADS + h], ex);
        }
    }
}

// ---------------- kernel C: edge pass 2 (weighted scatter) -----------------
__global__ void __launch_bounds__(256)
edge_pass2_kernel(const int* __restrict__ edge_index, float* __restrict__ out)
{
    const int lane   = threadIdx.x & 31;
    const int warp   = (blockIdx.x * blockDim.x + threadIdx.x) >> 5;
    const int nwarps = (gridDim.x * blockDim.x) >> 5;
    const int* src = edge_index;
    const int* dst = edge_index + N_EDGES;

    for (int e = warp; e < N_EDGES; e += nwarps) {
        int s = src[e], d = dst[e];
        float a0 = g_ex[(size_t)e * 2]     / (g_denom[(size_t)d * 2]     + 1e-16f);
        float a1 = g_ex[(size_t)e * 2 + 1] / (g_denom[(size_t)d * 2 + 1] + 1e-16f);
        float a  = (lane < 16) ? a0 : a1;   // cols [0,64) head0, [64,128) head1
        int c = lane * 4;
        float4 vv = *(const float4*)&g_v[(size_t)s * DIM + c];
        float4 ee = *(const float4*)&g_e[(size_t)e * DIM + c];
        float* op = out + (size_t)d * DIM + c;
        atomicAdd(op + 0, a * (vv.x + ee.x));
        atomicAdd(op + 1, a * (vv.y + ee.y));
        atomicAdd(op + 2, a * (vv.z + ee.z));
        atomicAdd(op + 3, a * (vv.w + ee.w));
    }
}

// ---------------- launch ----------------------------------------------------
extern "C" void kernel_launch(void* const* d_in, const int* in_sizes, int n_in,
                              void* d_out, int out_size)
{
    const float* x           = (const float*)d_in[0];
    const float* last_update = (const float*)d_in[1];
    const int*   edge_index  = (const int*)  d_in[2];
    const float* t           = (const float*)d_in[3];
    const float* msg         = (const float*)d_in[4];
    const float* wt          = (const float*)d_in[5];
    const float* bt          = (const float*)d_in[6];
    const float* Wq          = (const float*)d_in[7];
    const float* bq          = (const float*)d_in[8];
    const float* Wk          = (const float*)d_in[9];
    const float* bk          = (const float*)d_in[10];
    const float* Wv          = (const float*)d_in[11];
    const float* bv          = (const float*)d_in[12];
    const float* We          = (const float*)d_in[13];
    const float* Wskip       = (const float*)d_in[14];
    const float* bskip       = (const float*)d_in[15];
    float* out = (float*)d_out;

    cudaFuncSetAttribute(node_gemm_kernel,
                         cudaFuncAttributeMaxDynamicSharedMemorySize, SMEM_A_BYTES);
    cudaFuncSetAttribute(edge_pass1_kernel,
                         cudaFuncAttributeMaxDynamicSharedMemorySize, SMEM_B_BYTES);

    zero_denom_kernel<<<196, 1024>>>();

    int gridA = (N_NODES + 63) / 64;                 // 1563
    node_gemm_kernel<<<gridA, 256, SMEM_A_BYTES>>>(
        x, Wq, bq, Wk, bk, Wv, bv, Wskip, bskip, out);

    int gridB = N_EDGES / 64;                        // 9375 (exact)
    edge_pass1_kernel<<<gridB, 256, SMEM_B_BYTES>>>(
        last_update, edge_index, t, msg, wt, bt, We);

    edge_pass2_kernel<<<2048, 256>>>(edge_index, out);
}

// round 8
// speedup vs baseline: 2.5417x; 2.5417x over previous
#include <cuda_runtime.h>
#include <cuda_bf16.h>
#include <math.h>
#include <stdint.h>

#define N_NODES 100000
#define N_EDGES 600000
#define DIM     128
#define HEADS   2
#define NODE_TILES 782    // ceil(100000/128)
#define EDGE_TILES 4688   // ceil(600000/128)
#define SROW    272       // smem row stride in bytes (136 bf16) — conflict-free ldmatrix
#define SMEM_GEMM (4 * 128 * SROW)   // A_h, A_l, B_h, B_l = 139264 B

// ---------------- scratch (device globals; no runtime allocation) ----------
__device__ float g_q[(size_t)N_NODES * DIM];
__device__ float g_k[(size_t)N_NODES * DIM];
__device__ float g_v[(size_t)N_NODES * DIM];
__device__ float g_e[(size_t)N_EDGES * DIM];
__device__ float g_ex[(size_t)N_EDGES * HEADS];
__device__ float g_denom[(size_t)N_NODES * HEADS];
// pre-split weights, transposed to [n][k], bf16 pairs packed in uint32 (k-contiguous)
__device__ uint32_t g_Bh[5 * 8192];   // Wq,Wk,Wv,Wskip,We
__device__ uint32_t g_Bl[5 * 8192];

// ---------------- helpers ---------------------------------------------------
__device__ __forceinline__ void split_pack(float v0, float v1, uint32_t& hp, uint32_t& lp) {
    __nv_bfloat16 h0 = __float2bfloat16(v0), h1 = __float2bfloat16(v1);
    __nv_bfloat16 l0 = __float2bfloat16(v0 - __bfloat162float(h0));
    __nv_bfloat16 l1 = __float2bfloat16(v1 - __bfloat162float(h1));
    hp = ((uint32_t)__bfloat16_as_ushort(h1) << 16) | (uint32_t)__bfloat16_as_ushort(h0);
    lp = ((uint32_t)__bfloat16_as_ushort(l1) << 16) | (uint32_t)__bfloat16_as_ushort(l0);
}

__device__ __forceinline__ void ldsm_x4(uint32_t r[4], uint32_t addr) {
    asm volatile("ldmatrix.sync.aligned.m8n8.x4.shared.b16 {%0,%1,%2,%3}, [%4];"
                 : "=r"(r[0]), "=r"(r[1]), "=r"(r[2]), "=r"(r[3]) : "r"(addr));
}
__device__ __forceinline__ void ldsm_x2(uint32_t r[2], uint32_t addr) {
    asm volatile("ldmatrix.sync.aligned.m8n8.x2.shared.b16 {%0,%1}, [%2];"
                 : "=r"(r[0]), "=r"(r[1]) : "r"(addr));
}
__device__ __forceinline__ void mma_bf16(float c[4], const uint32_t a[4], const uint32_t b[2]) {
    asm volatile(
        "mma.sync.aligned.m16n8k16.row.col.f32.bf16.bf16.f32 "
        "{%0,%1,%2,%3}, {%4,%5,%6,%7}, {%8,%9}, {%0,%1,%2,%3};"
        : "+f"(c[0]), "+f"(c[1]), "+f"(c[2]), "+f"(c[3])
        : "r"(a[0]), "r"(a[1]), "r"(a[2]), "r"(a[3]), "r"(b[0]), "r"(b[1]));
}

// accurate-enough cos: Cody-Waite range reduction + MUFU
__device__ __forceinline__ float cos_acc(float x) {
    float k = rintf(x * 0.15915494309189535f);
    float r = fmaf(k, -6.28125f, x);              // 2*pi = 6.28125 + 1.9353...e-3
    r = fmaf(k, -1.9353071795864769e-3f, r);
    return __cosf(r);
}

// Shared warp-level GEMM: D[128,128] = A[128,128] @ B[128,128]^T (B stored [n][k])
// smem layout at byte offsets: A_h=0, A_l=34816, B_h=69632, B_l=104448.
// acc[2][8][4] per warp; warp wm=wid>>1 covers rows wm*32..+32, wn=wid&1 cols wn*64..+64.
#define GEMM_BODY(sbase, acc, lane, wm, wn)                                              \
    {                                                                                    \
        _Pragma("unroll")                                                                \
        for (int k0 = 0; k0 < 128; k0 += 16) {                                           \
            uint32_t ah[2][4], al[2][4];                                                 \
            _Pragma("unroll")                                                            \
            for (int fm = 0; fm < 2; fm++) {                                             \
                uint32_t off = (uint32_t)(((wm) * 32 + fm * 16 + ((lane) & 15)) * SROW   \
                               + (k0 + (((lane) >> 4) << 3)) * 2);                       \
                ldsm_x4(ah[fm], (sbase) + off);                                          \
                ldsm_x4(al[fm], (sbase) + 34816u + off);                                 \
            }                                                                            \
            _Pragma("unroll")                                                            \
            for (int fn = 0; fn < 8; fn++) {                                             \
                uint32_t boff = (uint32_t)(((wn) * 64 + fn * 8 + ((lane) & 7)) * SROW    \
                                + (k0 + ((((lane) >> 3) & 1) << 3)) * 2);                \
                uint32_t bh[2], bl[2];                                                   \
                ldsm_x2(bh, (sbase) + 69632u + boff);                                    \
                ldsm_x2(bl, (sbase) + 104448u + boff);                                   \
                _Pragma("unroll")                                                        \
                for (int fm = 0; fm < 2; fm++) {                                         \
                    mma_bf16(acc[fm][fn], ah[fm], bh);                                   \
                    mma_bf16(acc[fm][fn], ah[fm], bl);                                   \
                    mma_bf16(acc[fm][fn], al[fm], bh);                                   \
                }                                                                        \
            }                                                                            \
        }                                                                                \
    }

// ---------------- kernel Z: zero softmax denominators ----------------------
__global__ void zero_denom_kernel() {
    int i = blockIdx.x * blockDim.x + threadIdx.x;
    for (; i < N_NODES * HEADS; i += gridDim.x * blockDim.x) g_denom[i] = 0.0f;
}

// ---------------- conv_w: split + transpose 5 weight matrices --------------
__global__ void conv_w_kernel(const float* __restrict__ Wq, const float* __restrict__ Wk,
                              const float* __restrict__ Wv, const float* __restrict__ Wskip,
                              const float* __restrict__ We) {
    int idx = blockIdx.x * blockDim.x + threadIdx.x;
    if (idx >= 5 * 8192) return;
    const float* Ws[5] = {Wq, Wk, Wv, Wskip, We};
    int m  = idx >> 13;
    int n  = (idx >> 6) & 127;
    int kp = idx & 63;
    const float* W = Ws[m];
    float v0 = W[(2 * kp) * DIM + n];
    float v1 = W[(2 * kp + 1) * DIM + n];
    uint32_t hp, lp; split_pack(v0, v1, hp, lp);
    g_Bh[idx] = hp;   // [m][n][kp]
    g_Bl[idx] = lp;
}

// ---------------- node GEMM: q,k,v,skip via mma.sync split-bf16 ------------
__global__ void __launch_bounds__(256)
node_mma_kernel(const float* __restrict__ x,
                const float* __restrict__ bq, const float* __restrict__ bk,
                const float* __restrict__ bv, const float* __restrict__ bskip,
                float* __restrict__ out_skip)
{
    extern __shared__ char sm[];
    const uint32_t sbase = (uint32_t)__cvta_generic_to_shared(sm);
    const int tid  = threadIdx.x;
    const int lane = tid & 31, wid = tid >> 5;
    const int wm = wid >> 1, wn = wid & 1;
    const int tile = blockIdx.x;

    // load + split x tile into A_h / A_l smem
    for (int idx = tid; idx < 128 * 32; idx += 256) {
        int r = idx >> 5, j = idx & 31;
        int row = tile * 128 + r;
        float4 v = make_float4(0.f, 0.f, 0.f, 0.f);
        if (row < N_NODES) v = *(const float4*)&x[(size_t)row * DIM + j * 4];
        uint32_t h0, l0, h1, l1;
        split_pack(v.x, v.y, h0, l0);
        split_pack(v.z, v.w, h1, l1);
        uint32_t off = (uint32_t)(r * SROW + j * 8);
        *(uint2*)(sm + off)          = make_uint2(h0, h1);
        *(uint2*)(sm + 34816 + off)  = make_uint2(l0, l1);
    }

    const float* biases[4] = {bq, bk, bv, bskip};
    float* outs[4]; outs[0] = g_q; outs[1] = g_k; outs[2] = g_v; outs[3] = out_skip;

    for (int m = 0; m < 4; m++) {
        __syncthreads();   // A ready (m=0) / previous B readers done (m>0)
        {
            const uint4* srcH = (const uint4*)&g_Bh[m * 8192];
            const uint4* srcL = (const uint4*)&g_Bl[m * 8192];
            for (int i = tid; i < 2048; i += 256) {
                int r = i >> 4, ch = i & 15;
                uint32_t off = (uint32_t)(r * SROW + ch * 16);
                *(uint4*)(sm + 69632 + off)  = srcH[i];
                *(uint4*)(sm + 104448 + off) = srcL[i];
            }
        }
        __syncthreads();

        float acc[2][8][4];
        #pragma unroll
        for (int a = 0; a < 2; a++)
            #pragma unroll
            for (int b = 0; b < 8; b++)
                acc[a][b][0] = acc[a][b][1] = acc[a][b][2] = acc[a][b][3] = 0.f;

        GEMM_BODY(sbase, acc, lane, wm, wn);

        // epilogue: regs (+bias) -> global
        const float* bias = biases[m];
        float* O = outs[m];
        #pragma unroll
        for (int fm = 0; fm < 2; fm++) {
            #pragma unroll
            for (int fn = 0; fn < 8; fn++) {
                int col = wn * 64 + fn * 8 + (lane & 3) * 2;
                float2 b2 = *(const float2*)&bias[col];
                int r0 = tile * 128 + wm * 32 + fm * 16 + (lane >> 2);
                if (r0 < N_NODES) {
                    float2 o = make_float2(acc[fm][fn][0] + b2.x, acc[fm][fn][1] + b2.y);
                    *(float2*)&O[(size_t)r0 * DIM + col] = o;
                }
                int r1 = r0 + 8;
                if (r1 < N_NODES) {
                    float2 o = make_float2(acc[fm][fn][2] + b2.x, acc[fm][fn][3] + b2.y);
                    *(float2*)&O[(size_t)r1 * DIM + col] = o;
                }
            }
        }
    }
}

// ---------------- edge GEMM: e = [cos | msg] @ We --------------------------
__global__ void __launch_bounds__(256)
edge_mma_kernel(const float* __restrict__ last_update, const int* __restrict__ edge_index,
                const float* __restrict__ t, const float* __restrict__ msg,
                const float* __restrict__ wt, const float* __restrict__ bt)
{
    extern __shared__ char sm[];
    __shared__ float s_rel[128];
    const uint32_t sbase = (uint32_t)__cvta_generic_to_shared(sm);
    const int tid  = threadIdx.x;
    const int lane = tid & 31, wid = tid >> 5;
    const int wm = wid >> 1, wn = wid & 1;
    const int e0 = blockIdx.x * 128;
    const int* src = edge_index;

    // B = We (m=4) copy + rel times
    {
        const uint4* srcH = (const uint4*)&g_Bh[4 * 8192];
        const uint4* srcL = (const uint4*)&g_Bl[4 * 8192];
        for (int i = tid; i < 2048; i += 256) {
            int r = i >> 4, ch = i & 15;
            uint32_t off = (uint32_t)(r * SROW + ch * 16);
            *(uint4*)(sm + 69632 + off)  = srcH[i];
            *(uint4*)(sm + 104448 + off) = srcL[i];
        }
    }
    if (tid < 128) {
        int e = e0 + tid;
        s_rel[tid] = (e < N_EDGES) ? (last_update[src[e]] - t[e]) : 0.0f;
    }
    __syncthreads();

    // build attr tile (split bf16) into A_h / A_l
    for (int idx = tid; idx < 128 * 32; idx += 256) {
        int i = idx >> 5, j = idx & 31;
        int c0 = j * 4;
        int e = e0 + i;
        float v0 = 0.f, v1 = 0.f, v2 = 0.f, v3 = 0.f;
        if (e < N_EDGES) {
            if (c0 < 64) {
                float r = s_rel[i];
                v0 = cos_acc(fmaf(r, wt[c0],     bt[c0]));
                v1 = cos_acc(fmaf(r, wt[c0 + 1], bt[c0 + 1]));
                v2 = cos_acc(fmaf(r, wt[c0 + 2], bt[c0 + 2]));
                v3 = cos_acc(fmaf(r, wt[c0 + 3], bt[c0 + 3]));
            } else {
                float4 mv = *(const float4*)&msg[(size_t)e * 64 + (c0 - 64)];
                v0 = mv.x; v1 = mv.y; v2 = mv.z; v3 = mv.w;
            }
        }
        uint32_t h0, l0, h1, l1;
        split_pack(v0, v1, h0, l0);
        split_pack(v2, v3, h1, l1);
        uint32_t off = (uint32_t)(i * SROW + j * 8);
        *(uint2*)(sm + off)         = make_uint2(h0, h1);
        *(uint2*)(sm + 34816 + off) = make_uint2(l0, l1);
    }
    __syncthreads();

    float acc[2][8][4];
    #pragma unroll
    for (int a = 0; a < 2; a++)
        #pragma unroll
        for (int b = 0; b < 8; b++)
            acc[a][b][0] = acc[a][b][1] = acc[a][b][2] = acc[a][b][3] = 0.f;

    GEMM_BODY(sbase, acc, lane, wm, wn);

    // epilogue -> g_e
    #pragma unroll
    for (int fm = 0; fm < 2; fm++) {
        #pragma unroll
        for (int fn = 0; fn < 8; fn++) {
            int col = wn * 64 + fn * 8 + (lane & 3) * 2;
            int r0 = e0 + wm * 32 + fm * 16 + (lane >> 2);
            if (r0 < N_EDGES) {
                float2 o = make_float2(acc[fm][fn][0], acc[fm][fn][1]);
                *(float2*)&g_e[(size_t)r0 * DIM + col] = o;
            }
            int r1 = r0 + 8;
            if (r1 < N_EDGES) {
                float2 o = make_float2(acc[fm][fn][2], acc[fm][fn][3]);
                *(float2*)&g_e[(size_t)r1 * DIM + col] = o;
            }
        }
    }
}

// ---------------- alpha: logits + exp + denom (warp per edge) --------------
__global__ void __launch_bounds__(256)
alpha_kernel(const int* __restrict__ edge_index)
{
    const int lane = threadIdx.x & 31;
    const int warp = (blockIdx.x * blockDim.x + threadIdx.x) >> 5;
    const int nwarps = (gridDim.x * blockDim.x) >> 5;
    const int* src = edge_index;
    const int* dst = edge_index + N_EDGES;

    for (int e = warp; e < N_EDGES; e += nwarps) {
        int s = src[e], d = dst[e];
        int c = lane * 4;
        float4 q  = *(const float4*)&g_q[(size_t)d * DIM + c];
        float4 k  = *(const float4*)&g_k[(size_t)s * DIM + c];
        float4 ee = *(const float4*)&g_e[(size_t)e * DIM + c];
        float dot = q.x * (k.x + ee.x) + q.y * (k.y + ee.y)
                  + q.z * (k.z + ee.z) + q.w * (k.w + ee.w);
        #pragma unroll
        for (int o = 8; o > 0; o >>= 1) dot += __shfl_xor_sync(0xffffffffu, dot, o);
        if ((lane & 15) == 0) {
            int h = lane >> 4;
            float ex = expf(dot * 0.125f);   // / sqrt(64)
            g_ex[(size_t)e * HEADS + h] = ex;
            atomicAdd(&g_denom[(size_t)d * HEADS + h], ex);
        }
    }
}

// ---------------- pass2: weighted scatter-add ------------------------------
__global__ void __launch_bounds__(256)
edge_pass2_kernel(const int* __restrict__ edge_index, float* __restrict__ out)
{
    const int lane   = threadIdx.x & 31;
    const int warp   = (blockIdx.x * blockDim.x + threadIdx.x) >> 5;
    const int nwarps = (gridDim.x * blockDim.x) >> 5;
    const int* src = edge_index;
    const int* dst = edge_index + N_EDGES;

    for (int e = warp; e < N_EDGES; e += nwarps) {
        int s = src[e], d = dst[e];
        float a0 = g_ex[(size_t)e * 2]     / (g_denom[(size_t)d * 2]     + 1e-16f);
        float a1 = g_ex[(size_t)e * 2 + 1] / (g_denom[(size_t)d * 2 + 1] + 1e-16f);
        float a  = (lane < 16) ? a0 : a1;
        int c = lane * 4;
        float4 vv = *(const float4*)&g_v[(size_t)s * DIM + c];
        float4 ee = *(const float4*)&g_e[(size_t)e * DIM + c];
        float* op = out + (size_t)d * DIM + c;
        atomicAdd(op + 0, a * (vv.x + ee.x));
        atomicAdd(op + 1, a * (vv.y + ee.y));
        atomicAdd(op + 2, a * (vv.z + ee.z));
        atomicAdd(op + 3, a * (vv.w + ee.w));
    }
}

// ---------------- launch ----------------------------------------------------
extern "C" void kernel_launch(void* const* d_in, const int* in_sizes, int n_in,
                              void* d_out, int out_size)
{
    const float* x           = (const float*)d_in[0];
    const float* last_update = (const float*)d_in[1];
    const int*   edge_index  = (const int*)  d_in[2];
    const float* t           = (const float*)d_in[3];
    const float* msg         = (const float*)d_in[4];
    const float* wt          = (const float*)d_in[5];
    const float* bt          = (const float*)d_in[6];
    const float* Wq          = (const float*)d_in[7];
    const float* bq          = (const float*)d_in[8];
    const float* Wk          = (const float*)d_in[9];
    const float* bk          = (const float*)d_in[10];
    const float* Wv          = (const float*)d_in[11];
    const float* bv          = (const float*)d_in[12];
    const float* We          = (const float*)d_in[13];
    const float* Wskip       = (const float*)d_in[14];
    const float* bskip       = (const float*)d_in[15];
    float* out = (float*)d_out;

    cudaFuncSetAttribute(node_mma_kernel,
                         cudaFuncAttributeMaxDynamicSharedMemorySize, SMEM_GEMM);
    cudaFuncSetAttribute(edge_mma_kernel,
                         cudaFuncAttributeMaxDynamicSharedMemorySize, SMEM_GEMM);

    zero_denom_kernel<<<196, 1024>>>();
    conv_w_kernel<<<(5 * 8192 + 255) / 256, 256>>>(Wq, Wk, Wv, Wskip, We);

    node_mma_kernel<<<NODE_TILES, 256, SMEM_GEMM>>>(x, bq, bk, bv, bskip, out);
    edge_mma_kernel<<<EDGE_TILES, 256, SMEM_GEMM>>>(last_update, edge_index, t, msg, wt, bt);

    alpha_kernel<<<2048, 256>>>(edge_index);
    edge_pass2_kernel<<<2048, 256>>>(edge_index, out);
}

// round 9
// speedup vs baseline: 3.1957x; 1.2573x over previous
#include <cuda_runtime.h>
#include <cuda_bf16.h>
#include <math.h>
#include <stdint.h>

#define N_NODES 100000
#define N_EDGES 600000
#define DIM     128
#define HEADS   2
#define NODE_TILES 1563   // ceil(100000/64)
#define EDGE_TILES 9375   // 600000/64
#define SROW    272       // smem row stride in bytes (136 bf16) — conflict-free ldmatrix
// smem offsets: A_h=0 (64 rows), A_l=17408, B_h=34816 (128 rows), B_l=69632
#define OFF_AL 17408u
#define OFF_BH 34816u
#define OFF_BL 69632u
#define SMEM_GEMM (OFF_BL + 128 * SROW)   // 104448 B -> 2 CTAs/SM

// ---------------- scratch (device globals; no runtime allocation) ----------
__device__ float g_q[(size_t)N_NODES * DIM];
__device__ float g_k[(size_t)N_NODES * DIM];
__device__ float g_v[(size_t)N_NODES * DIM];
__device__ float g_e[(size_t)N_EDGES * DIM];
__device__ float g_ex[(size_t)N_EDGES * HEADS];
__device__ float g_denom[(size_t)N_NODES * HEADS];
// pre-split weights, transposed to [n][k], bf16 pairs packed in uint32 (k-contiguous)
__device__ uint32_t g_Bh[5 * 8192];   // Wq,Wk,Wv,Wskip,We
__device__ uint32_t g_Bl[5 * 8192];

// ---------------- helpers ---------------------------------------------------
__device__ __forceinline__ void split_pack(float v0, float v1, uint32_t& hp, uint32_t& lp) {
    __nv_bfloat16 h0 = __float2bfloat16(v0), h1 = __float2bfloat16(v1);
    __nv_bfloat16 l0 = __float2bfloat16(v0 - __bfloat162float(h0));
    __nv_bfloat16 l1 = __float2bfloat16(v1 - __bfloat162float(h1));
    hp = ((uint32_t)__bfloat16_as_ushort(h1) << 16) | (uint32_t)__bfloat16_as_ushort(h0);
    lp = ((uint32_t)__bfloat16_as_ushort(l1) << 16) | (uint32_t)__bfloat16_as_ushort(l0);
}

__device__ __forceinline__ void ldsm_x4(uint32_t r[4], uint32_t addr) {
    asm volatile("ldmatrix.sync.aligned.m8n8.x4.shared.b16 {%0,%1,%2,%3}, [%4];"
                 : "=r"(r[0]), "=r"(r[1]), "=r"(r[2]), "=r"(r[3]) : "r"(addr));
}
__device__ __forceinline__ void mma_bf16(float c[4], const uint32_t a[4], const uint32_t b[2]) {
    asm volatile(
        "mma.sync.aligned.m16n8k16.row.col.f32.bf16.bf16.f32 "
        "{%0,%1,%2,%3}, {%4,%5,%6,%7}, {%8,%9}, {%0,%1,%2,%3};"
        : "+f"(c[0]), "+f"(c[1]), "+f"(c[2]), "+f"(c[3])
        : "r"(a[0]), "r"(a[1]), "r"(a[2]), "r"(a[3]), "r"(b[0]), "r"(b[1]));
}

// accurate-enough cos: Cody-Waite range reduction + MUFU
__device__ __forceinline__ float cos_acc(float x) {
    float k = rintf(x * 0.15915494309189535f);
    float r = fmaf(k, -6.28125f, x);              // 2*pi = 6.28125 + 1.9353...e-3
    r = fmaf(k, -1.9353071795864769e-3f, r);
    return __cosf(r);
}

// Warp-level GEMM: D[64,128] = A[64,128] @ B[128,128]^T (B stored [n][k]).
// 8 warps: wm = wid>>1 in 0..3 -> rows wm*16..+16; wn = wid&1 -> cols wn*64..+64.
// acc[8][4]. B fragments loaded pairwise via ldmatrix.x4 (two n-frags per op).
#define GEMM_BODY(sbase, acc, lane, wm, wn)                                              \
    {                                                                                    \
        const uint32_t a_row = (uint32_t)(((wm) * 16 + ((lane) & 15)) * SROW             \
                                          + (((lane) >> 4) << 4));                       \
        const uint32_t b_row = (uint32_t)((((wn) * 64 + (((lane) >> 4) << 3)             \
                                          + ((lane) & 7)) * SROW)                        \
                                          + ((((lane) >> 3) & 1) << 4));                 \
        _Pragma("unroll")                                                                \
        for (int k0 = 0; k0 < 128; k0 += 16) {                                           \
            uint32_t ah[4], al[4];                                                       \
            ldsm_x4(ah, (sbase) + a_row + k0 * 2);                                       \
            ldsm_x4(al, (sbase) + OFF_AL + a_row + k0 * 2);                              \
            _Pragma("unroll")                                                            \
            for (int fp = 0; fp < 4; fp++) {                                             \
                uint32_t bo = b_row + (uint32_t)(fp * 16 * SROW) + (uint32_t)(k0 * 2);   \
                uint32_t bh[4], bl[4];                                                   \
                ldsm_x4(bh, (sbase) + OFF_BH + bo);                                      \
                ldsm_x4(bl, (sbase) + OFF_BL + bo);                                      \
                mma_bf16(acc[2 * fp],     ah, &bh[0]);                                   \
                mma_bf16(acc[2 * fp],     ah, &bl[0]);                                   \
                mma_bf16(acc[2 * fp],     al, &bh[0]);                                   \
                mma_bf16(acc[2 * fp + 1], ah, &bh[2]);                                   \
                mma_bf16(acc[2 * fp + 1], ah, &bl[2]);                                   \
                mma_bf16(acc[2 * fp + 1], al, &bh[2]);                                   \
            }                                                                            \
        }                                                                                \
    }

// ---------------- kernel Z: zero softmax denominators ----------------------
__global__ void zero_denom_kernel() {
    int i = blockIdx.x * blockDim.x + threadIdx.x;
    for (; i < N_NODES * HEADS; i += gridDim.x * blockDim.x) g_denom[i] = 0.0f;
}

// ---------------- conv_w: split + transpose 5 weight matrices --------------
__global__ void conv_w_kernel(const float* __restrict__ Wq, const float* __restrict__ Wk,
                              const float* __restrict__ Wv, const float* __restrict__ Wskip,
                              const float* __restrict__ We) {
    int idx = blockIdx.x * blockDim.x + threadIdx.x;
    if (idx >= 5 * 8192) return;
    const float* Ws[5] = {Wq, Wk, Wv, Wskip, We};
    int m  = idx >> 13;
    int n  = (idx >> 6) & 127;
    int kp = idx & 63;
    const float* W = Ws[m];
    float v0 = W[(2 * kp) * DIM + n];
    float v1 = W[(2 * kp + 1) * DIM + n];
    uint32_t hp, lp; split_pack(v0, v1, hp, lp);
    g_Bh[idx] = hp;   // [m][n][kp]
    g_Bl[idx] = lp;
}

// ---------------- node GEMM: q,k,v,skip via mma.sync split-bf16 ------------
__global__ void __launch_bounds__(256, 2)
node_mma_kernel(const float* __restrict__ x,
                const float* __restrict__ bq, const float* __restrict__ bk,
                const float* __restrict__ bv, const float* __restrict__ bskip,
                float* __restrict__ out_skip)
{
    extern __shared__ char sm[];
    const uint32_t sbase = (uint32_t)__cvta_generic_to_shared(sm);
    const int tid  = threadIdx.x;
    const int lane = tid & 31, wid = tid >> 5;
    const int wm = wid >> 1, wn = wid & 1;
    const int tile = blockIdx.x;

    // load + split x tile (64 rows) into A_h / A_l smem
    for (int idx = tid; idx < 64 * 32; idx += 256) {
        int r = idx >> 5, j = idx & 31;
        int row = tile * 64 + r;
        float4 v = make_float4(0.f, 0.f, 0.f, 0.f);
        if (row < N_NODES) v = *(const float4*)&x[(size_t)row * DIM + j * 4];
        uint32_t h0, l0, h1, l1;
        split_pack(v.x, v.y, h0, l0);
        split_pack(v.z, v.w, h1, l1);
        uint32_t off = (uint32_t)(r * SROW + j * 8);
        *(uint2*)(sm + off)          = make_uint2(h0, h1);
        *(uint2*)(sm + OFF_AL + off) = make_uint2(l0, l1);
    }

    const float* biases[4] = {bq, bk, bv, bskip};
    float* outs[4]; outs[0] = g_q; outs[1] = g_k; outs[2] = g_v; outs[3] = out_skip;

    for (int m = 0; m < 4; m++) {
        __syncthreads();   // A ready (m=0) / previous B readers done (m>0)
        {
            const uint4* srcH = (const uint4*)&g_Bh[m * 8192];
            const uint4* srcL = (const uint4*)&g_Bl[m * 8192];
            for (int i = tid; i < 2048; i += 256) {
                int r = i >> 4, ch = i & 15;
                uint32_t off = (uint32_t)(r * SROW + ch * 16);
                *(uint4*)(sm + OFF_BH + off) = srcH[i];
                *(uint4*)(sm + OFF_BL + off) = srcL[i];
            }
        }
        __syncthreads();

        float acc[8][4];
        #pragma unroll
        for (int b = 0; b < 8; b++)
            acc[b][0] = acc[b][1] = acc[b][2] = acc[b][3] = 0.f;

        GEMM_BODY(sbase, acc, lane, wm, wn);

        // epilogue: regs (+bias) -> global
        const float* bias = biases[m];
        float* O = outs[m];
        #pragma unroll
        for (int fn = 0; fn < 8; fn++) {
            int col = wn * 64 + fn * 8 + (lane & 3) * 2;
            float2 b2 = *(const float2*)&bias[col];
            int r0 = tile * 64 + wm * 16 + (lane >> 2);
            if (r0 < N_NODES) {
                float2 o = make_float2(acc[fn][0] + b2.x, acc[fn][1] + b2.y);
                *(float2*)&O[(size_t)r0 * DIM + col] = o;
            }
            int r1 = r0 + 8;
            if (r1 < N_NODES) {
                float2 o = make_float2(acc[fn][2] + b2.x, acc[fn][3] + b2.y);
                *(float2*)&O[(size_t)r1 * DIM + col] = o;
            }
        }
    }
}

// ---------------- edge GEMM: e = [cos | msg] @ We --------------------------
__global__ void __launch_bounds__(256, 2)
edge_mma_kernel(const float* __restrict__ last_update, const int* __restrict__ edge_index,
                const float* __restrict__ t, const float* __restrict__ msg,
                const float* __restrict__ wt, const float* __restrict__ bt)
{
    extern __shared__ char sm[];
    __shared__ float s_rel[64];
    const uint32_t sbase = (uint32_t)__cvta_generic_to_shared(sm);
    const int tid  = threadIdx.x;
    const int lane = tid & 31, wid = tid >> 5;
    const int wm = wid >> 1, wn = wid & 1;
    const int e0 = blockIdx.x * 64;
    const int* src = edge_index;

    // B = We (m=4) copy + rel times
    {
        const uint4* srcH = (const uint4*)&g_Bh[4 * 8192];
        const uint4* srcL = (const uint4*)&g_Bl[4 * 8192];
        for (int i = tid; i < 2048; i += 256) {
            int r = i >> 4, ch = i & 15;
            uint32_t off = (uint32_t)(r * SROW + ch * 16);
            *(uint4*)(sm + OFF_BH + off) = srcH[i];
            *(uint4*)(sm + OFF_BL + off) = srcL[i];
        }
    }
    if (tid < 64) {
        int e = e0 + tid;
        s_rel[tid] = (e < N_EDGES) ? (last_update[src[e]] - t[e]) : 0.0f;
    }
    __syncthreads();

    // build attr tile (split bf16) into A_h / A_l
    for (int idx = tid; idx < 64 * 32; idx += 256) {
        int i = idx >> 5, j = idx & 31;
        int c0 = j * 4;
        int e = e0 + i;
        float v0 = 0.f, v1 = 0.f, v2 = 0.f, v3 = 0.f;
        if (e < N_EDGES) {
            if (c0 < 64) {
                float r = s_rel[i];
                v0 = cos_acc(fmaf(r, wt[c0],     bt[c0]));
                v1 = cos_acc(fmaf(r, wt[c0 + 1], bt[c0 + 1]));
                v2 = cos_acc(fmaf(r, wt[c0 + 2], bt[c0 + 2]));
                v3 = cos_acc(fmaf(r, wt[c0 + 3], bt[c0 + 3]));
            } else {
                float4 mv = *(const float4*)&msg[(size_t)e * 64 + (c0 - 64)];
                v0 = mv.x; v1 = mv.y; v2 = mv.z; v3 = mv.w;
            }
        }
        uint32_t h0, l0, h1, l1;
        split_pack(v0, v1, h0, l0);
        split_pack(v2, v3, h1, l1);
        uint32_t off = (uint32_t)(i * SROW + j * 8);
        *(uint2*)(sm + off)          = make_uint2(h0, h1);
        *(uint2*)(sm + OFF_AL + off) = make_uint2(l0, l1);
    }
    __syncthreads();

    float acc[8][4];
    #pragma unroll
    for (int b = 0; b < 8; b++)
        acc[b][0] = acc[b][1] = acc[b][2] = acc[b][3] = 0.f;

    GEMM_BODY(sbase, acc, lane, wm, wn);

    // epilogue -> g_e
    #pragma unroll
    for (int fn = 0; fn < 8; fn++) {
        int col = wn * 64 + fn * 8 + (lane & 3) * 2;
        int r0 = e0 + wm * 16 + (lane >> 2);
        if (r0 < N_EDGES) {
            float2 o = make_float2(acc[fn][0], acc[fn][1]);
            *(float2*)&g_e[(size_t)r0 * DIM + col] = o;
        }
        int r1 = r0 + 8;
        if (r1 < N_EDGES) {
            float2 o = make_float2(acc[fn][2], acc[fn][3]);
            *(float2*)&g_e[(size_t)r1 * DIM + col] = o;
        }
    }
}

// ---------------- alpha: logits + exp + denom (warp per edge) --------------
__global__ void __launch_bounds__(256)
alpha_kernel(const int* __restrict__ edge_index)
{
    const int lane = threadIdx.x & 31;
    const int warp = (blockIdx.x * blockDim.x + threadIdx.x) >> 5;
    const int nwarps = (gridDim.x * blockDim.x) >> 5;
    const int* src = edge_index;
    const int* dst = edge_index + N_EDGES;

    for (int e = warp; e < N_EDGES; e += nwarps) {
        int s = src[e], d = dst[e];
        int c = lane * 4;
        float4 q  = *(const float4*)&g_q[(size_t)d * DIM + c];
        float4 k  = *(const float4*)&g_k[(size_t)s * DIM + c];
        float4 ee = *(const float4*)&g_e[(size_t)e * DIM + c];
        float dot = q.x * (k.x + ee.x) + q.y * (k.y + ee.y)
                  + q.z * (k.z + ee.z) + q.w * (k.w + ee.w);
        #pragma unroll
        for (int o = 8; o > 0; o >>= 1) dot += __shfl_xor_sync(0xffffffffu, dot, o);
        if ((lane & 15) == 0) {
            int h = lane >> 4;
            float ex = expf(dot * 0.125f);   // / sqrt(64)
            g_ex[(size_t)e * HEADS + h] = ex;
            atomicAdd(&g_denom[(size_t)d * HEADS + h], ex);
        }
    }
}

// ---------------- pass2: weighted scatter-add ------------------------------
__global__ void __launch_bounds__(256)
edge_pass2_kernel(const int* __restrict__ edge_index, float* __restrict__ out)
{
    const int lane   = threadIdx.x & 31;
    const int warp   = (blockIdx.x * blockDim.x + threadIdx.x) >> 5;
    const int nwarps = (gridDim.x * blockDim.x) >> 5;
    const int* src = edge_index;
    const int* dst = edge_index + N_EDGES;

    for (int e = warp; e < N_EDGES; e += nwarps) {
        int s = src[e], d = dst[e];
        float a0 = g_ex[(size_t)e * 2]     / (g_denom[(size_t)d * 2]     + 1e-16f);
        float a1 = g_ex[(size_t)e * 2 + 1] / (g_denom[(size_t)d * 2 + 1] + 1e-16f);
        float a  = (lane < 16) ? a0 : a1;
        int c = lane * 4;
        float4 vv = *(const float4*)&g_v[(size_t)s * DIM + c];
        float4 ee = *(const float4*)&g_e[(size_t)e * DIM + c];
        float* op = out + (size_t)d * DIM + c;
        atomicAdd(op + 0, a * (vv.x + ee.x));
        atomicAdd(op + 1, a * (vv.y + ee.y));
        atomicAdd(op + 2, a * (vv.z + ee.z));
        atomicAdd(op + 3, a * (vv.w + ee.w));
    }
}

// ---------------- launch ----------------------------------------------------
extern "C" void kernel_launch(void* const* d_in, const int* in_sizes, int n_in,
                              void* d_out, int out_size)
{
    const float* x           = (const float*)d_in[0];
    const float* last_update = (const float*)d_in[1];
    const int*   edge_index  = (const int*)  d_in[2];
    const float* t           = (const float*)d_in[3];
    const float* msg         = (const float*)d_in[4];
    const float* wt          = (const float*)d_in[5];
    const float* bt          = (const float*)d_in[6];
    const float* Wq          = (const float*)d_in[7];
    const float* bq          = (const float*)d_in[8];
    const float* Wk          = (const float*)d_in[9];
    const float* bk          = (const float*)d_in[10];
    const float* Wv          = (const float*)d_in[11];
    const float* bv          = (const float*)d_in[12];
    const float* We          = (const float*)d_in[13];
    const float* Wskip       = (const float*)d_in[14];
    const float* bskip       = (const float*)d_in[15];
    float* out = (float*)d_out;

    cudaFuncSetAttribute(node_mma_kernel,
                         cudaFuncAttributeMaxDynamicSharedMemorySize, SMEM_GEMM);
    cudaFuncSetAttribute(edge_mma_kernel,
                         cudaFuncAttributeMaxDynamicSharedMemorySize, SMEM_GEMM);

    zero_denom_kernel<<<196, 1024>>>();
    conv_w_kernel<<<(5 * 8192 + 255) / 256, 256>>>(Wq, Wk, Wv, Wskip, We);

    node_mma_kernel<<<NODE_TILES, 256, SMEM_GEMM>>>(x, bq, bk, bv, bskip, out);
    edge_mma_kernel<<<EDGE_TILES, 256, SMEM_GEMM>>>(last_update, edge_index, t, msg, wt, bt);

    alpha_kernel<<<2048, 256>>>(edge_index);
    edge_pass2_kernel<<<2048, 256>>>(edge_index, out);
}

// round 13
// speedup vs baseline: 3.9855x; 1.2472x over previous
#include <cuda_runtime.h>
#include <cuda_bf16.h>
#include <math.h>
#include <stdint.h>

#define N_NODES 100000
#define N_EDGES 600000
#define DIM     128
#define HEADS   2
#define NODE_TILES 1563   // ceil(100000/64)
#define EDGE_TILES 9375   // 600000/64
#define NODE_GROUPS 74    // CTAs per weight matrix
#define NODE_CTAS  (4 * NODE_GROUPS)   // 296
#define EDGE_CTAS  586
#define SROW    272       // smem row stride in bytes (136 bf16) — conflict-free ldmatrix
// smem offsets: A_h=0 (64 rows), A_l=17408, B_h=34816 (128 rows), B_l=69632
#define OFF_AL 17408u
#define OFF_BH 34816u
#define OFF_BL 69632u
#define SMEM_GEMM (OFF_BL + 128 * SROW)   // 104448 B -> 2 CTAs/SM

// ---------------- scratch (device globals; no runtime allocation) ----------
__device__ float g_q[(size_t)N_NODES * DIM];
__device__ float g_k[(size_t)N_NODES * DIM];
__device__ float g_v[(size_t)N_NODES * DIM];
__device__ float g_e[(size_t)N_EDGES * DIM];
__device__ float g_ex[(size_t)N_EDGES * HEADS];
__device__ float g_denom[(size_t)N_NODES * HEADS];
// pre-split weights, transposed to [n][k], bf16 pairs packed in uint32 (k-contiguous)
__device__ uint32_t g_Bh[5 * 8192];   // Wq,Wk,Wv,Wskip,We
__device__ uint32_t g_Bl[5 * 8192];

// ---------------- helpers ---------------------------------------------------
__device__ __forceinline__ void split_pack(float v0, float v1, uint32_t& hp, uint32_t& lp) {
    __nv_bfloat16 h0 = __float2bfloat16(v0), h1 = __float2bfloat16(v1);
    __nv_bfloat16 l0 = __float2bfloat16(v0 - __bfloat162float(h0));
    __nv_bfloat16 l1 = __float2bfloat16(v1 - __bfloat162float(h1));
    hp = ((uint32_t)__bfloat16_as_ushort(h1) << 16) | (uint32_t)__bfloat16_as_ushort(h0);
    lp = ((uint32_t)__bfloat16_as_ushort(l1) << 16) | (uint32_t)__bfloat16_as_ushort(l0);
}

__device__ __forceinline__ void ldsm_x4(uint32_t r[4], uint32_t addr) {
    asm volatile("ldmatrix.sync.aligned.m8n8.x4.shared.b16 {%0,%1,%2,%3}, [%4];"
                 : "=r"(r[0]), "=r"(r[1]), "=r"(r[2]), "=r"(r[3]) : "r"(addr));
}
__device__ __forceinline__ void mma_bf16(float c[4], const uint32_t a[4], const uint32_t b[2]) {
    asm volatile(
        "mma.sync.aligned.m16n8k16.row.col.f32.bf16.bf16.f32 "
        "{%0,%1,%2,%3}, {%4,%5,%6,%7}, {%8,%9}, {%0,%1,%2,%3};"
        : "+f"(c[0]), "+f"(c[1]), "+f"(c[2]), "+f"(c[3])
        : "r"(a[0]), "r"(a[1]), "r"(a[2]), "r"(a[3]), "r"(b[0]), "r"(b[1]));
}
__device__ __forceinline__ void red_add_v4(float* p, float4 v) {
    asm volatile("red.global.add.v4.f32 [%0], {%1,%2,%3,%4};"
                 :: "l"(p), "f"(v.x), "f"(v.y), "f"(v.z), "f"(v.w) : "memory");
}
__device__ __forceinline__ void red_add_v2(float* p, float a, float b) {
    asm volatile("red.global.add.v2.f32 [%0], {%1,%2};"
                 :: "l"(p), "f"(a), "f"(b) : "memory");
}

// accurate-enough cos: Cody-Waite range reduction + MUFU
__device__ __forceinline__ float cos_acc(float x) {
    float k = rintf(x * 0.15915494309189535f);
    float r = fmaf(k, -6.28125f, x);              // 2*pi = 6.28125 + 1.9353...e-3
    r = fmaf(k, -1.9353071795864769e-3f, r);
    return __cosf(r);
}

// Warp-level GEMM: D[64,128] = A[64,128] @ B[128,128]^T (B stored [n][k]).
// 8 warps: wm = wid>>1 in 0..3 -> rows wm*16..+16; wn = wid&1 -> cols wn*64..+64.
// acc[8][4]. B fragments loaded pairwise via ldmatrix.x4 (two n-frags per op).
#define GEMM_BODY(sbase, acc, lane, wm, wn)                                              \
    {                                                                                    \
        const uint32_t a_row = (uint32_t)(((wm) * 16 + ((lane) & 15)) * SROW             \
                                          + (((lane) >> 4) << 4));                       \
        const uint32_t b_row = (uint32_t)((((wn) * 64 + (((lane) >> 4) << 3)             \
                                          + ((lane) & 7)) * SROW)                        \
                                          + ((((lane) >> 3) & 1) << 4));                 \
        _Pragma("unroll")                                                                \
        for (int k0 = 0; k0 < 128; k0 += 16) {                                           \
            uint32_t ah[4], al[4];                                                       \
            ldsm_x4(ah, (sbase) + a_row + k0 * 2);                                       \
            ldsm_x4(al, (sbase) + OFF_AL + a_row + k0 * 2);                              \
            _Pragma("unroll")                                                            \
            for (int fp = 0; fp < 4; fp++) {                                             \
                uint32_t bo = b_row + (uint32_t)(fp * 16 * SROW) + (uint32_t)(k0 * 2);   \
                uint32_t bh[4], bl[4];                                                   \
                ldsm_x4(bh, (sbase) + OFF_BH + bo);                                      \
                ldsm_x4(bl, (sbase) + OFF_BL + bo);                                      \
                mma_bf16(acc[2 * fp],     ah, &bh[0]);                                   \
                mma_bf16(acc[2 * fp],     ah, &bl[0]);                                   \
                mma_bf16(acc[2 * fp],     al, &bh[0]);                                   \
                mma_bf16(acc[2 * fp + 1], ah, &bh[2]);                                   \
                mma_bf16(acc[2 * fp + 1], ah, &bl[2]);                                   \
                mma_bf16(acc[2 * fp + 1], al, &bh[2]);                                   \
            }                                                                            \
        }                                                                                \
    }

// ---------------- kernel Z: zero softmax denominators ----------------------
__global__ void zero_denom_kernel() {
    int i = blockIdx.x * blockDim.x + threadIdx.x;
    for (; i < N_NODES * HEADS; i += gridDim.x * blockDim.x) g_denom[i] = 0.0f;
}

// ---------------- conv_w: split + transpose 5 weight matrices --------------
__global__ void conv_w_kernel(const float* __restrict__ Wq, const float* __restrict__ Wk,
                              const float* __restrict__ Wv, const float* __restrict__ Wskip,
                              const float* __restrict__ We) {
    int idx = blockIdx.x * blockDim.x + threadIdx.x;
    if (idx >= 5 * 8192) return;
    const float* Ws[5] = {Wq, Wk, Wv, Wskip, We};
    int m  = idx >> 13;
    int n  = (idx >> 6) & 127;
    int kp = idx & 63;
    const float* W = Ws[m];
    float v0 = W[(2 * kp) * DIM + n];
    float v1 = W[(2 * kp + 1) * DIM + n];
    uint32_t hp, lp; split_pack(v0, v1, hp, lp);
    g_Bh[idx] = hp;   // [m][n][kp]
    g_Bl[idx] = lp;
}

// ---------------- fused GEMM: node q/k/v/skip + edge e ---------------------
// CTAs [0, NODE_CTAS): matrix m = bx&3, group j = bx>>2; B[m] resident, loop
// over row tiles j, j+74, ...  CTAs [NODE_CTAS, +EDGE_CTAS): We resident,
// loop over edge tiles j2, j2+586, ...
__global__ void __launch_bounds__(256, 2)
gemm_fused_kernel(const float* __restrict__ x,
                  const float* __restrict__ bq, const float* __restrict__ bk,
                  const float* __restrict__ bv, const float* __restrict__ bskip,
                  float* __restrict__ out_skip,
                  const float* __restrict__ last_update, const int* __restrict__ edge_index,
                  const float* __restrict__ t, const float* __restrict__ msg,
                  const float* __restrict__ wt, const float* __restrict__ bt)
{
    extern __shared__ char sm[];
    __shared__ float s_rel[64];
    const uint32_t sbase = (uint32_t)__cvta_generic_to_shared(sm);
    const int tid  = threadIdx.x;
    const int lane = tid & 31, wid = tid >> 5;
    const int wm = wid >> 1, wn = wid & 1;

    if (blockIdx.x < NODE_CTAS) {
        // ---------------- node part ----------------
        const int m = blockIdx.x & 3;
        const int j = blockIdx.x >> 2;
        {
            const uint4* srcH = (const uint4*)&g_Bh[m * 8192];
            const uint4* srcL = (const uint4*)&g_Bl[m * 8192];
            for (int i = tid; i < 2048; i += 256) {
                int r = i >> 4, ch = i & 15;
                uint32_t off = (uint32_t)(r * SROW + ch * 16);
                *(uint4*)(sm + OFF_BH + off) = srcH[i];
                *(uint4*)(sm + OFF_BL + off) = srcL[i];
            }
        }
        const float* bias = (m == 0) ? bq : (m == 1) ? bk : (m == 2) ? bv : bskip;
        float* O = (m == 0) ? g_q : (m == 1) ? g_k : (m == 2) ? g_v : out_skip;

        for (int tile = j; tile < NODE_TILES; tile += NODE_GROUPS) {
            // load + split x tile (64 rows) into A_h / A_l
            for (int idx = tid; idx < 64 * 32; idx += 256) {
                int r = idx >> 5, jj = idx & 31;
                int row = tile * 64 + r;
                float4 v = make_float4(0.f, 0.f, 0.f, 0.f);
                if (row < N_NODES) v = *(const float4*)&x[(size_t)row * DIM + jj * 4];
                uint32_t h0, l0, h1, l1;
                split_pack(v.x, v.y, h0, l0);
                split_pack(v.z, v.w, h1, l1);
                uint32_t off = (uint32_t)(r * SROW + jj * 8);
                *(uint2*)(sm + off)          = make_uint2(h0, h1);
                *(uint2*)(sm + OFF_AL + off) = make_uint2(l0, l1);
            }
            __syncthreads();

            float acc[8][4];
            #pragma unroll
            for (int b = 0; b < 8; b++)
                acc[b][0] = acc[b][1] = acc[b][2] = acc[b][3] = 0.f;
            GEMM_BODY(sbase, acc, lane, wm, wn);

            #pragma unroll
            for (int fn = 0; fn < 8; fn++) {
                int col = wn * 64 + fn * 8 + (lane & 3) * 2;
                float2 b2 = *(const float2*)&bias[col];
                int r0 = tile * 64 + wm * 16 + (lane >> 2);
                if (r0 < N_NODES) {
                    float2 o = make_float2(acc[fn][0] + b2.x, acc[fn][1] + b2.y);
                    *(float2*)&O[(size_t)r0 * DIM + col] = o;
                }
                int r1 = r0 + 8;
                if (r1 < N_NODES) {
                    float2 o = make_float2(acc[fn][2] + b2.x, acc[fn][3] + b2.y);
                    *(float2*)&O[(size_t)r1 * DIM + col] = o;
                }
            }
            __syncthreads();   // all A readers done before next overwrite
        }
    } else {
        // ---------------- edge part ----------------
        const int j = blockIdx.x - NODE_CTAS;
        const int* src = edge_index;
        {
            const uint4* srcH = (const uint4*)&g_Bh[4 * 8192];
            const uint4* srcL = (const uint4*)&g_Bl[4 * 8192];
            for (int i = tid; i < 2048; i += 256) {
                int r = i >> 4, ch = i & 15;
                uint32_t off = (uint32_t)(r * SROW + ch * 16);
                *(uint4*)(sm + OFF_BH + off) = srcH[i];
                *(uint4*)(sm + OFF_BL + off) = srcL[i];
            }
        }

        for (int tile = j; tile < EDGE_TILES; tile += EDGE_CTAS) {
            const int e0 = tile * 64;
            if (tid < 64) {
                int e = e0 + tid;
                s_rel[tid] = last_update[src[e]] - t[e];
            }
            __syncthreads();

            // build attr tile (split bf16) into A_h / A_l (E divisible by 64)
            for (int idx = tid; idx < 64 * 32; idx += 256) {
                int i = idx >> 5, jj = idx & 31;
                int c0 = jj * 4;
                int e = e0 + i;
                float v0, v1, v2, v3;
                if (c0 < 64) {
                    float r = s_rel[i];
                    v0 = cos_acc(fmaf(r, wt[c0],     bt[c0]));
                    v1 = cos_acc(fmaf(r, wt[c0 + 1], bt[c0 + 1]));
                    v2 = cos_acc(fmaf(r, wt[c0 + 2], bt[c0 + 2]));
                    v3 = cos_acc(fmaf(r, wt[c0 + 3], bt[c0 + 3]));
                } else {
                    float4 mv = *(const float4*)&msg[(size_t)e * 64 + (c0 - 64)];
                    v0 = mv.x; v1 = mv.y; v2 = mv.z; v3 = mv.w;
                }
                uint32_t h0, l0, h1, l1;
                split_pack(v0, v1, h0, l0);
                split_pack(v2, v3, h1, l1);
                uint32_t off = (uint32_t)(i * SROW + jj * 8);
                *(uint2*)(sm + off)          = make_uint2(h0, h1);
                *(uint2*)(sm + OFF_AL + off) = make_uint2(l0, l1);
            }
            __syncthreads();

            float acc[8][4];
            #pragma unroll
            for (int b = 0; b < 8; b++)
                acc[b][0] = acc[b][1] = acc[b][2] = acc[b][3] = 0.f;
            GEMM_BODY(sbase, acc, lane, wm, wn);

            #pragma unroll
            for (int fn = 0; fn < 8; fn++) {
                int col = wn * 64 + fn * 8 + (lane & 3) * 2;
                int r0 = e0 + wm * 16 + (lane >> 2);
                float2 o0 = make_float2(acc[fn][0], acc[fn][1]);
                *(float2*)&g_e[(size_t)r0 * DIM + col] = o0;
                float2 o1 = make_float2(acc[fn][2], acc[fn][3]);
                *(float2*)&g_e[(size_t)(r0 + 8) * DIM + col] = o1;
            }
            __syncthreads();   // readers of s_rel / A done before next overwrite
        }
    }
}

// ---------------- alpha: logits + exp + denom (warp per edge) --------------
__global__ void __launch_bounds__(256)
alpha_kernel(const int* __restrict__ edge_index)
{
    const int lane = threadIdx.x & 31;
    const int warp = (blockIdx.x * blockDim.x + threadIdx.x) >> 5;
    const int nwarps = (gridDim.x * blockDim.x) >> 5;
    const int* src = edge_index;
    const int* dst = edge_index + N_EDGES;

    for (int e = warp; e < N_EDGES; e += nwarps) {
        int s = src[e], d = dst[e];
        int c = lane * 4;
        float4 q  = *(const float4*)&g_q[(size_t)d * DIM + c];
        float4 k  = *(const float4*)&g_k[(size_t)s * DIM + c];
        float4 ee = *(const float4*)&g_e[(size_t)e * DIM + c];
        float dot = q.x * (k.x + ee.x) + q.y * (k.y + ee.y)
                  + q.z * (k.z + ee.z) + q.w * (k.w + ee.w);
        #pragma unroll
        for (int o = 8; o > 0; o >>= 1) dot += __shfl_xor_sync(0xffffffffu, dot, o);
        float ex = 0.f;
        if ((lane & 15) == 0) ex = expf(dot * 0.125f);   // / sqrt(64)
        float ex1 = __shfl_sync(0xffffffffu, ex, 16);
        if (lane == 0) {
            *(float2*)&g_ex[(size_t)e * 2] = make_float2(ex, ex1);
            red_add_v2(&g_denom[(size_t)d * 2], ex, ex1);
        }
    }
}

// ---------------- pass2: weighted scatter-add (vector reductions) ----------
__global__ void __launch_bounds__(256)
edge_pass2_kernel(const int* __restrict__ edge_index, float* __restrict__ out)
{
    const int lane   = threadIdx.x & 31;
    const int warp   = (blockIdx.x * blockDim.x + threadIdx.x) >> 5;
    const int nwarps = (gridDim.x * blockDim.x) >> 5;
    const int* src = edge_index;
    const int* dst = edge_index + N_EDGES;

    for (int e = warp; e < N_EDGES; e += nwarps) {
        int s = src[e], d = dst[e];
        float a0 = g_ex[(size_t)e * 2]     / (g_denom[(size_t)d * 2]     + 1e-16f);
        float a1 = g_ex[(size_t)e * 2 + 1] / (g_denom[(size_t)d * 2 + 1] + 1e-16f);
        float a  = (lane < 16) ? a0 : a1;
        int c = lane * 4;
        float4 vv = *(const float4*)&g_v[(size_t)s * DIM + c];
        float4 ee = *(const float4*)&g_e[(size_t)e * DIM + c];
        float4 val = make_float4(a * (vv.x + ee.x), a * (vv.y + ee.y),
                                 a * (vv.z + ee.z), a * (vv.w + ee.w));
        red_add_v4(out + (size_t)d * DIM + c, val);
    }
}

// ---------------- launch ----------------------------------------------------
extern "C" void kernel_launch(void* const* d_in, const int* in_sizes, int n_in,
                              void* d_out, int out_size)
{
    const float* x           = (const float*)d_in[0];
    const float* last_update = (const float*)d_in[1];
    const int*   edge_index  = (const int*)  d_in[2];
    const float* t           = (const float*)d_in[3];
    const float* msg         = (const float*)d_in[4];
    const float* wt          = (const float*)d_in[5];
    const float* bt          = (const float*)d_in[6];
    const float* Wq          = (const float*)d_in[7];
    const float* bq          = (const float*)d_in[8];
    const float* Wk          = (const float*)d_in[9];
    const float* bk          = (const float*)d_in[10];
    const float* Wv          = (const float*)d_in[11];
    const float* bv          = (const float*)d_in[12];
    const float* We          = (const float*)d_in[13];
    const float* Wskip       = (const float*)d_in[14];
    const float* bskip       = (const float*)d_in[15];
    float* out = (float*)d_out;

    cudaFuncSetAttribute(gemm_fused_kernel,
                         cudaFuncAttributeMaxDynamicSharedMemorySize, SMEM_GEMM);

    zero_denom_kernel<<<196, 1024>>>();
    conv_w_kernel<<<(5 * 8192 + 255) / 256, 256>>>(Wq, Wk, Wv, Wskip, We);

    gemm_fused_kernel<<<NODE_CTAS + EDGE_CTAS, 256, SMEM_GEMM>>>(
        x, bq, bk, bv, bskip, out,
        last_update, edge_index, t, msg, wt, bt);

    alpha_kernel<<<2048, 256>>>(edge_index);
    edge_pass2_kernel<<<2048, 256>>>(edge_index, out);
}